// round 16
// baseline (speedup 1.0000x reference)
#include <cuda_runtime.h>
#include <cuda_bf16.h>
#include <cuda_fp16.h>
#include <cstdint>
#include <math.h>

#define SEQ 2048
#define EMB 1024
#define NH  16
#define HD  64

// Q prescale: log2(e)/32 — S computed in log2 domain, P = 2^S.
#define QSCALE 0.0450842151f

// ============================ helpers ============================
#define CP_ASYNC16(dst, src) \
    asm volatile("cp.async.cg.shared.global [%0], [%1], 16;" :: "r"(dst), "l"(src) : "memory")
#define CP_ASYNC_COMMIT() asm volatile("cp.async.commit_group;" ::: "memory")
#define CP_ASYNC_WAIT0()  asm volatile("cp.async.wait_group 0;" ::: "memory")
#define CP_ASYNC_WAIT1()  asm volatile("cp.async.wait_group 1;" ::: "memory")

#define LDSM4(r, addr) \
    asm volatile("ldmatrix.sync.aligned.m8n8.x4.shared.b16 {%0,%1,%2,%3}, [%4];" \
        : "=r"((r)[0]), "=r"((r)[1]), "=r"((r)[2]), "=r"((r)[3]) : "r"(addr))

__device__ __forceinline__ void mma16816(float* d, const uint32_t* a, const uint32_t* b) {
    asm volatile(
        "mma.sync.aligned.m16n8k16.row.col.f32.bf16.bf16.f32 "
        "{%0,%1,%2,%3}, {%4,%5,%6,%7}, {%8,%9}, {%0,%1,%2,%3};"
        : "+f"(d[0]), "+f"(d[1]), "+f"(d[2]), "+f"(d[3])
        : "r"(a[0]), "r"(a[1]), "r"(a[2]), "r"(a[3]), "r"(b[0]), "r"(b[1]));
}

__device__ __forceinline__ void mma16816h(float* d, const uint32_t* a, const uint32_t* b) {
    asm volatile(
        "mma.sync.aligned.m16n8k16.row.col.f32.f16.f16.f32 "
        "{%0,%1,%2,%3}, {%4,%5,%6,%7}, {%8,%9}, {%0,%1,%2,%3};"
        : "+f"(d[0]), "+f"(d[1]), "+f"(d[2]), "+f"(d[3])
        : "r"(a[0]), "r"(a[1]), "r"(a[2]), "r"(a[3]), "r"(b[0]), "r"(b[1]));
}

__device__ __forceinline__ uint32_t pack2(float x, float y) {
    __nv_bfloat162 t = __floats2bfloat162_rn(x, y);
    return *(uint32_t*)&t;
}
__device__ __forceinline__ uint32_t hpack2(float x, float y) {
    __half2 t = __floats2half2_rn(x, y);
    return *(uint32_t*)&t;
}
__device__ __forceinline__ float ex2f(float x) {
    float r;
    asm("ex2.approx.ftz.f32 %0, %1;" : "=f"(r) : "f"(x));
    return r;
}

// ============================ device scratch ============================
__device__ __align__(256) float g_Vf[SEQ * EMB];
__device__ __align__(256) float g_invsum[NH * SEQ];

__device__ __align__(256) __nv_bfloat16 g_xhi[SEQ * EMB],  g_xlo[SEQ * EMB];
__device__ __align__(256) __nv_bfloat16 g_Qhi[SEQ * EMB];                      // [NH][SEQ][64], prescaled
__device__ __align__(256) __nv_bfloat16 g_Khi[SEQ * EMB];                      // [NH][SEQ][64]
__device__ __align__(256) __half        g_Vt16[EMB * SEQ];                     // V^T [EMB][SEQ] fp16
__device__ __align__(256) __nv_bfloat16 g_chi[SEQ * EMB],  g_clo[SEQ * EMB];   // ctx [SEQ][EMB]

// ============================ split / transpose ============================
__global__ __launch_bounds__(256)
void split_pair(const float* __restrict__ src, __nv_bfloat16* __restrict__ hi,
                __nv_bfloat16* __restrict__ lo, int n)
{
    int i = blockIdx.x * 256 + threadIdx.x;
    if (i < n) {
        float v = src[i];
        __nv_bfloat16 h = __float2bfloat16(v);
        hi[i] = h;
        lo[i] = __float2bfloat16(v - __bfloat162float(h));
    }
}

__global__ __launch_bounds__(256)
void transpose_f16(const float* __restrict__ V, __half* __restrict__ out)
{
    __shared__ float t[32][33];
    int e0 = blockIdx.x * 32, s0 = blockIdx.y * 32;
    int tx = threadIdx.x, ty = threadIdx.y;  // 32 x 8
#pragma unroll
    for (int i = 0; i < 32; i += 8)
        t[ty + i][tx] = V[(size_t)(s0 + ty + i) * EMB + e0 + tx];
    __syncthreads();
#pragma unroll
    for (int i = 0; i < 32; i += 8) {
        size_t o = (size_t)(e0 + ty + i) * SEQ + s0 + tx;
        out[o] = __float2half(t[tx][ty + i]);
    }
}

// ============================ HMMA NT projection GEMM ============================
// BM=256, BN=64. kind 0 (QKV): z0: Wq -> Qhi packed (1-prod, prescaled);
// z1: Wk -> Khi packed (1-prod); z2: Wv -> fp32 (3-prod). kind 1 (Wo, 3-prod).
__global__ __launch_bounds__(256, 1)
void proj_gemm(const __nv_bfloat16* __restrict__ Ahi, const __nv_bfloat16* __restrict__ Alo,
               const float* __restrict__ W0, const float* __restrict__ W1,
               const float* __restrict__ W2,
               const float* __restrict__ b0, const float* __restrict__ b1,
               const float* __restrict__ b2,
               __nv_bfloat16* __restrict__ P0hi, __nv_bfloat16* __restrict__ P1hi,
               float* __restrict__ Cf, int kind)
{
    constexpr int APLANE = 256 * 80;
    constexpr int BPLANE = 64 * 80;
    constexpr int STAGE  = 2 * APLANE + 2 * BPLANE;  // 51200
    constexpr int NC = EMB / 32;

    extern __shared__ char dsm[];
    const uint32_t smem0 = (uint32_t)__cvta_generic_to_shared(dsm);

    const int tid  = threadIdx.x;
    const int wid  = tid >> 5;
    const int lane = tid & 31;
    const int wm = wid & 3;
    const int wn = wid >> 2;
    const int rl = lane >> 2;

    const int z = blockIdx.z;
    const float* Bf   = (z == 0) ? W0 : (z == 1) ? W1 : W2;
    const float* bias = (z == 0) ? b0 : (z == 1) ? b1 : b2;
    const int mode = (kind == 1 || z == 2) ? 0 : 2;
    const bool three = (kind == 1 || z == 2);
    __nv_bfloat16* Chi = (z == 0) ? P0hi : P1hi;
    const float oscale = (mode == 2 && z == 0) ? QSCALE : 1.0f;

    const int row0 = blockIdx.y * 256;
    const int col0 = blockIdx.x * 64;

    float acc[4][4][4];
#pragma unroll
    for (int mi = 0; mi < 4; mi++)
#pragma unroll
        for (int ni = 0; ni < 4; ni++)
#pragma unroll
            for (int j = 0; j < 4; j++) acc[mi][ni][j] = 0.f;

    const int nA = three ? 2048 : 1024;
    auto load_A = [&](int c) {
        const uint32_t sb = smem0 + (c % 3) * STAGE;
        for (int i = tid; i < nA; i += 256) {
            int pl = i >> 10;
            int rem = i & 1023;
            int r = rem >> 2, g = rem & 3;
            const __nv_bfloat16* src =
                (pl ? Alo : Ahi) + (size_t)(row0 + r) * EMB + c * 32 + g * 8;
            CP_ASYNC16(sb + pl * APLANE + r * 80 + g * 16, src);
        }
        CP_ASYNC_COMMIT();
    };

    float4 breg[2];
    const int br = tid >> 2;
    const int bseg = (tid & 3) * 8;
    auto ldg_B = [&](int c) {
        const float* src = Bf + (size_t)(col0 + br) * EMB + c * 32 + bseg;
        breg[0] = *(const float4*)(src);
        breg[1] = *(const float4*)(src + 4);
    };
    auto sts_B = [&](int c) {
        const uint32_t off = (uint32_t)((c % 3) * STAGE + 2 * APLANE + br * 80 + bseg * 2);
        uint4 hi4;
        uint32_t* h = (uint32_t*)&hi4;
        float4 v0 = breg[0], v1 = breg[1];
        h[0] = pack2(v0.x, v0.y); h[1] = pack2(v0.z, v0.w);
        h[2] = pack2(v1.x, v1.y); h[3] = pack2(v1.z, v1.w);
        *(uint4*)(dsm + off) = hi4;
        if (three) {
            uint4 lo4;
            uint32_t* l = (uint32_t*)&lo4;
            __nv_bfloat162* hb = (__nv_bfloat162*)h;
            l[0] = pack2(v0.x - __low2float(hb[0]), v0.y - __high2float(hb[0]));
            l[1] = pack2(v0.z - __low2float(hb[1]), v0.w - __high2float(hb[1]));
            l[2] = pack2(v1.x - __low2float(hb[2]), v1.y - __high2float(hb[2]));
            l[3] = pack2(v1.z - __low2float(hb[3]), v1.w - __high2float(hb[3]));
            *(uint4*)(dsm + off + BPLANE) = lo4;
        }
    };

    auto compute = [&](int c) {
        const uint32_t sb = smem0 + (c % 3) * STAGE;
        const uint32_t aAddr = sb + (wm * 64 + (lane & 15)) * 80 + (lane >> 4) * 16;
        const uint32_t bAddr = sb + 2 * APLANE
            + (wn * 32 + (lane >> 4) * 8 + (lane & 7)) * 80 + ((lane >> 3) & 1) * 16;
#pragma unroll
        for (int kk = 0; kk < 2; kk++) {
            uint32_t a0[4][4], a1[4][4];
#pragma unroll
            for (int mi = 0; mi < 4; mi++)
                LDSM4(a0[mi], aAddr + mi * 16 * 80 + kk * 32);
            if (three) {
#pragma unroll
                for (int mi = 0; mi < 4; mi++)
                    LDSM4(a1[mi], aAddr + APLANE + mi * 16 * 80 + kk * 32);
            }
            uint32_t b0r[4][2], b1r[4][2];
#pragma unroll
            for (int np = 0; np < 2; np++) {
                uint32_t r4[4];
                LDSM4(r4, bAddr + np * 16 * 80 + kk * 32);
                b0r[2 * np][0] = r4[0]; b0r[2 * np][1] = r4[1];
                b0r[2 * np + 1][0] = r4[2]; b0r[2 * np + 1][1] = r4[3];
            }
            if (three) {
#pragma unroll
                for (int np = 0; np < 2; np++) {
                    uint32_t r4[4];
                    LDSM4(r4, bAddr + BPLANE + np * 16 * 80 + kk * 32);
                    b1r[2 * np][0] = r4[0]; b1r[2 * np][1] = r4[1];
                    b1r[2 * np + 1][0] = r4[2]; b1r[2 * np + 1][1] = r4[3];
                }
            }
#pragma unroll
            for (int mi = 0; mi < 4; mi++)
#pragma unroll
                for (int ni = 0; ni < 4; ni++)
                    mma16816(acc[mi][ni], a0[mi], b0r[ni]);
            if (three) {
#pragma unroll
                for (int mi = 0; mi < 4; mi++)
#pragma unroll
                    for (int ni = 0; ni < 4; ni++) {
                        mma16816(acc[mi][ni], a0[mi], b1r[ni]);
                        mma16816(acc[mi][ni], a1[mi], b0r[ni]);
                    }
            }
        }
    };

    ldg_B(0); sts_B(0); load_A(0);
    ldg_B(1); sts_B(1); load_A(1);
    ldg_B(2);

    for (int c = 0; c < NC; c++) {
        if (c + 1 < NC) { CP_ASYNC_WAIT1(); } else { CP_ASYNC_WAIT0(); }
        __syncthreads();
        compute(c);
        if (c + 2 < NC) {
            sts_B(c + 2);
            load_A(c + 2);
            if (c + 3 < NC) ldg_B(c + 3);
        }
    }

    const int cl = (lane & 3) * 2;
#pragma unroll
    for (int mi = 0; mi < 4; mi++) {
        const int r = row0 + wm * 64 + mi * 16 + rl;
#pragma unroll
        for (int ni = 0; ni < 4; ni++) {
            const int cc = col0 + wn * 32 + ni * 8 + cl;
            const float bb0 = bias[cc], bb1 = bias[cc + 1];
            float v00 = (acc[mi][ni][0] + bb0) * oscale;
            float v01 = (acc[mi][ni][1] + bb1) * oscale;
            float v10 = (acc[mi][ni][2] + bb0) * oscale;
            float v11 = (acc[mi][ni][3] + bb1) * oscale;
            if (mode == 0) {
                *(float2*)(Cf + (size_t)r * EMB + cc) = make_float2(v00, v01);
                *(float2*)(Cf + (size_t)(r + 8) * EMB + cc) = make_float2(v10, v11);
            } else {
                size_t o0 = (size_t)(cc >> 6) * ((size_t)SEQ * 64) + (size_t)r * 64 + (cc & 63);
                size_t o1 = o0 + 8 * 64;
                *(uint32_t*)(Chi + o0) = pack2(v00, v01);
                *(uint32_t*)(Chi + o1) = pack2(v10, v11);
            }
        }
    }
}

// ============================ attention phase 1 (512 threads) ============================
// 16 warps = 8(m: 16 rows) x 2(n / PV k-half). Same arithmetic as before.
static constexpr int FA_OFF_K   = 18432;
static constexpr int FA_OFF_V   = 55296;
static constexpr int FA_OFF_RED = 90112;
static constexpr int FA_SMEM    = 91648;

__global__ __launch_bounds__(512, 1)
void attention_phase1(const __nv_bfloat16* __restrict__ Qhi,
                      const __nv_bfloat16* __restrict__ Khi,
                      const __half* __restrict__ Vt16,
                      float* __restrict__ invsum,
                      __nv_bfloat16* __restrict__ chi, __nv_bfloat16* __restrict__ clo)
{
    extern __shared__ char sm[];
    const uint32_t sb = (uint32_t)__cvta_generic_to_shared(sm);

    const int tid  = threadIdx.x;
    const int lane = tid & 31, wid = tid >> 5;
    const int wm = wid & 7;      // 8 m-tiles of 16 rows
    const int wn = wid >> 3;     // 2 halves
    const int rl = lane >> 2;
    const int h  = blockIdx.y;
    const int q0 = blockIdx.x * 128;

    auto loadQ = [&]() {
        for (int i = tid; i < 1024; i += 512) {
            int r = i >> 3, g = i & 7;
            const __nv_bfloat16* src = Qhi + ((size_t)h * SEQ + q0 + r) * 64 + g * 8;
            CP_ASYNC16(sb + r * 144 + g * 16, src);
        }
    };
    auto loadK = [&](int j) {
        int st = (j & 1) * 18432;
        for (int i = tid; i < 1024; i += 512) {
            int r = i >> 3, g = i & 7;
            const __nv_bfloat16* src = Khi + ((size_t)h * SEQ + j * 128 + r) * 64 + g * 8;
            CP_ASYNC16(sb + FA_OFF_K + st + r * 144 + g * 16, src);
        }
    };
    auto loadV = [&](int j) {
        int st = (j & 1) * 17408;
        for (int i = tid; i < 1024; i += 512) {
            int d = i >> 4, g = i & 15;
            const __half* src = Vt16 + ((size_t)(h * 64 + d)) * SEQ + j * 128 + g * 8;
            CP_ASYNC16(sb + FA_OFF_V + st + d * 272 + g * 16, src);
        }
    };

    const uint32_t aBase  = sb + (wm * 16 + (lane & 15)) * 144 + (lane >> 4) * 16;
    const uint32_t bBaseK = sb + FA_OFF_K + (wn * 64 + (lane >> 4) * 8 + (lane & 7)) * 144
                            + ((lane >> 3) & 1) * 16;
    const uint32_t bBaseV = sb + FA_OFF_V + ((lane >> 4) * 8 + (lane & 7)) * 272
                            + ((lane >> 3) & 1) * 16 + wn * 128;

    float ctx[8][4];
#pragma unroll
    for (int nd = 0; nd < 8; nd++)
#pragma unroll
        for (int j = 0; j < 4; j++) ctx[nd][j] = 0.f;
    float rs[2] = {0.f, 0.f};

    loadQ(); loadK(0); loadV(0); CP_ASYNC_COMMIT();
    loadK(1); loadV(1); CP_ASYNC_COMMIT();

    for (int j = 0; j < 16; j++) {
        if (j < 15) { CP_ASYNC_WAIT1(); } else { CP_ASYNC_WAIT0(); }
        __syncthreads();

        float s[8][4];
#pragma unroll
        for (int ni = 0; ni < 8; ni++)
#pragma unroll
            for (int q = 0; q < 4; q++) s[ni][q] = 0.f;

        const uint32_t kst = (uint32_t)((j & 1) * 18432);
#pragma unroll
        for (int kk = 0; kk < 4; kk++) {
            uint32_t a[4];
            LDSM4(a, aBase + kk * 32);
            uint32_t bk[8][2];
#pragma unroll
            for (int np = 0; np < 4; np++) {
                uint32_t r4[4];
                LDSM4(r4, bBaseK + kst + np * 2304 + kk * 32);
                bk[2 * np][0] = r4[0]; bk[2 * np][1] = r4[1];
                bk[2 * np + 1][0] = r4[2]; bk[2 * np + 1][1] = r4[3];
            }
#pragma unroll
            for (int ni = 0; ni < 8; ni++)
                mma16816(s[ni], a, bk[ni]);
        }

        // PV: P = 2^s via ex2.approx.f16x2
        const uint32_t vst = (uint32_t)((j & 1) * 17408);
#pragma unroll
        for (int kk = 0; kk < 4; kk++) {
            uint32_t bv[8][2];
#pragma unroll
            for (int np = 0; np < 4; np++) {
                uint32_t r4[4];
                LDSM4(r4, bBaseV + vst + np * 4352 + kk * 32);
                bv[2 * np][0] = r4[0]; bv[2 * np][1] = r4[1];
                bv[2 * np + 1][0] = r4[2]; bv[2 * np + 1][1] = r4[3];
            }
            const int e = 2 * kk, o = 2 * kk + 1;
            uint32_t ah[4];
            ah[0] = hpack2(s[e][0], s[e][1]);
            ah[1] = hpack2(s[e][2], s[e][3]);
            ah[2] = hpack2(s[o][0], s[o][1]);
            ah[3] = hpack2(s[o][2], s[o][3]);
#pragma unroll
            for (int q = 0; q < 4; q++)
                asm("ex2.approx.f16x2 %0, %0;" : "+r"(ah[q]));
            __half2 t0 = __hadd2(*(__half2*)&ah[0], *(__half2*)&ah[2]);
            __half2 t1 = __hadd2(*(__half2*)&ah[1], *(__half2*)&ah[3]);
            float2 f0 = __half22float2(t0), f1 = __half22float2(t1);
            rs[0] += f0.x + f0.y;
            rs[1] += f1.x + f1.y;
#pragma unroll
            for (int nd = 0; nd < 8; nd++)
                mma16816h(ctx[nd], ah, bv[nd]);
        }
        __syncthreads();
        if (j + 2 < 16) { loadK(j + 2); loadV(j + 2); CP_ASYNC_COMMIT(); }
    }

#pragma unroll
    for (int i = 0; i < 2; i++) {
        rs[i] += __shfl_xor_sync(0xffffffffu, rs[i], 1);
        rs[i] += __shfl_xor_sync(0xffffffffu, rs[i], 2);
    }
    float* redp = (float*)(sm + FA_OFF_RED);            // [2][128]
    float* invp = (float*)(sm + FA_OFF_RED + 1024);     // [128]
    if ((lane & 3) == 0) {
        redp[wn * 128 + wm * 16 + rl]     = rs[0];
        redp[wn * 128 + wm * 16 + rl + 8] = rs[1];
    }
    __syncthreads();
    if (tid < 128) {
        float inv = 1.0f / (redp[tid] + redp[128 + tid]);
        invp[tid] = inv;
        invsum[(size_t)h * SEQ + q0 + tid] = inv;
    }
    __syncthreads();

    float* credp = (float*)(sm + FA_OFF_V);   // [128][64] fp32 (32 KB, fits V area)
    if (wn == 1) {
        const int r = wm * 16 + rl;
#pragma unroll
        for (int nd = 0; nd < 8; nd++) {
            const int c = nd * 8 + (lane & 3) * 2;
            *(float2*)(credp + r * 64 + c)       = make_float2(ctx[nd][0], ctx[nd][1]);
            *(float2*)(credp + (r + 8) * 64 + c) = make_float2(ctx[nd][2], ctx[nd][3]);
        }
    }
    __syncthreads();
    if (wn == 0) {
        const int r = wm * 16 + rl;
        const float i0 = invp[r], i1 = invp[r + 8];
#pragma unroll
        for (int nd = 0; nd < 8; nd++) {
            const int c = nd * 8 + (lane & 3) * 2;
            float2 p0 = *(float2*)(credp + r * 64 + c);
            float2 p1 = *(float2*)(credp + (r + 8) * 64 + c);
            float v00 = (ctx[nd][0] + p0.x) * i0;
            float v01 = (ctx[nd][1] + p0.y) * i0;
            float v10 = (ctx[nd][2] + p1.x) * i1;
            float v11 = (ctx[nd][3] + p1.y) * i1;
            size_t o0 = (size_t)(q0 + r) * EMB + h * 64 + c;
            size_t o1 = (size_t)(q0 + r + 8) * EMB + h * 64 + c;
            uint32_t h0 = pack2(v00, v01), h1 = pack2(v10, v11);
            __nv_bfloat162 hb0 = *(__nv_bfloat162*)&h0;
            __nv_bfloat162 hb1 = *(__nv_bfloat162*)&h1;
            uint32_t l0 = pack2(v00 - __low2float(hb0), v01 - __high2float(hb0));
            uint32_t l1 = pack2(v10 - __low2float(hb1), v11 - __high2float(hb1));
            *(uint32_t*)(chi + o0) = h0;
            *(uint32_t*)(chi + o1) = h1;
            *(uint32_t*)(clo + o0) = l0;
            *(uint32_t*)(clo + o1) = l1;
        }
    }
}

// ============================ attention phase 2 ============================
static constexpr int P2_OFF_K   = 18432;
static constexpr int P2_OFF_INV = 55296;
static constexpr int P2_SMEM    = 55808;

__global__ __launch_bounds__(256)
void attention_phase2(const __nv_bfloat16* __restrict__ Qhi,
                      const __nv_bfloat16* __restrict__ Khi,
                      const float* __restrict__ invsum,
                      float* __restrict__ attn)
{
    extern __shared__ char sm[];
    const uint32_t sb = (uint32_t)__cvta_generic_to_shared(sm);

    const int tid  = threadIdx.x;
    const int lane = tid & 31, wid = tid >> 5;
    const int wm = wid & 3, wn = wid >> 2;
    const int rl = lane >> 2;
    const int h  = blockIdx.y;
    const int q0 = blockIdx.x * 128;

    float* invp = (float*)(sm + P2_OFF_INV);
    if (tid < 128) invp[tid] = invsum[(size_t)h * SEQ + q0 + tid];

    auto loadQ = [&]() {
        for (int i = tid; i < 1024; i += 256) {
            int r = i >> 3, g = i & 7;
            const __nv_bfloat16* src = Qhi + ((size_t)h * SEQ + q0 + r) * 64 + g * 8;
            CP_ASYNC16(sb + r * 144 + g * 16, src);
        }
    };
    auto loadK = [&](int j) {
        int st = (j & 1) * 18432;
        for (int i = tid; i < 1024; i += 256) {
            int r = i >> 3, g = i & 7;
            const __nv_bfloat16* src = Khi + ((size_t)h * SEQ + j * 128 + r) * 64 + g * 8;
            CP_ASYNC16(sb + P2_OFF_K + st + r * 144 + g * 16, src);
        }
    };

    const uint32_t aBase  = sb + (wm * 32 + (lane & 15)) * 144 + (lane >> 4) * 16;
    const uint32_t bBaseK = sb + P2_OFF_K + (wn * 64 + (lane >> 4) * 8 + (lane & 7)) * 144
                            + ((lane >> 3) & 1) * 16;

    loadQ(); loadK(0); CP_ASYNC_COMMIT();
    loadK(1); CP_ASYNC_COMMIT();

    for (int j = 0; j < 16; j++) {
        if (j < 15) { CP_ASYNC_WAIT1(); } else { CP_ASYNC_WAIT0(); }
        __syncthreads();

        float s[2][8][4];
#pragma unroll
        for (int mi = 0; mi < 2; mi++)
#pragma unroll
            for (int ni = 0; ni < 8; ni++)
#pragma unroll
                for (int q = 0; q < 4; q++) s[mi][ni][q] = 0.f;

        const uint32_t kst = (uint32_t)((j & 1) * 18432);
#pragma unroll
        for (int kk = 0; kk < 4; kk++) {
            uint32_t a[2][4];
#pragma unroll
            for (int mi = 0; mi < 2; mi++)
                LDSM4(a[mi], aBase + mi * 2304 + kk * 32);
            uint32_t bk[8][2];
#pragma unroll
            for (int np = 0; np < 4; np++) {
                uint32_t r4[4];
                LDSM4(r4, bBaseK + kst + np * 2304 + kk * 32);
                bk[2 * np][0] = r4[0]; bk[2 * np][1] = r4[1];
                bk[2 * np + 1][0] = r4[2]; bk[2 * np + 1][1] = r4[3];
            }
#pragma unroll
            for (int mi = 0; mi < 2; mi++)
#pragma unroll
                for (int ni = 0; ni < 8; ni++)
                    mma16816(s[mi][ni], a[mi], bk[ni]);
        }

#pragma unroll
        for (int mi = 0; mi < 2; mi++) {
            const int r = wm * 32 + mi * 16 + rl;
            const float i0 = invp[r], i1 = invp[r + 8];
#pragma unroll
            for (int ni = 0; ni < 8; ni++) {
                const int c = wn * 64 + ni * 8 + (lane & 3) * 2;
                float2 v0 = make_float2(ex2f(s[mi][ni][0]) * i0,
                                        ex2f(s[mi][ni][1]) * i0);
                float2 v1 = make_float2(ex2f(s[mi][ni][2]) * i1,
                                        ex2f(s[mi][ni][3]) * i1);
                size_t base = ((size_t)h * SEQ + q0 + r) * (size_t)SEQ + j * 128 + c;
                *(float2*)(attn + base) = v0;
                *(float2*)(attn + base + 8 * SEQ) = v1;
            }
        }
        __syncthreads();
        if (j + 2 < 16) { loadK(j + 2); CP_ASYNC_COMMIT(); }
    }
}

// ============================ host launch ============================
static constexpr int SMEM3 = 3 * (2 * 256 * 80 + 2 * 64 * 80);  // 153600

extern "C" void kernel_launch(void* const* d_in, const int* in_sizes, int n_in,
                              void* d_out, int out_size)
{
    const float* x  = (const float*)d_in[0];
    const float* Wq = (const float*)d_in[1];
    const float* bq = (const float*)d_in[2];
    const float* Wk = (const float*)d_in[3];
    const float* bk = (const float*)d_in[4];
    const float* Wv = (const float*)d_in[5];
    const float* bv = (const float*)d_in[6];
    const float* Wo = (const float*)d_in[7];
    const float* bo = (const float*)d_in[8];

    float* out  = (float*)d_out;
    float* attn = out + (size_t)SEQ * EMB;

#define SYM(p, s) void* p##_v; cudaGetSymbolAddress(&p##_v, s);
    SYM(Vf, g_Vf) SYM(invs, g_invsum)
    SYM(xhi, g_xhi) SYM(xlo, g_xlo)
    SYM(Qhi, g_Qhi) SYM(Khi, g_Khi) SYM(Vt16, g_Vt16)
    SYM(chi, g_chi) SYM(clo, g_clo)
#undef SYM
#define BF(p) ((__nv_bfloat16*)p##_v)
#define FL(p) ((float*)p##_v)

    cudaFuncSetAttribute(proj_gemm, cudaFuncAttributeMaxDynamicSharedMemorySize, SMEM3);
    cudaFuncSetAttribute(attention_phase1, cudaFuncAttributeMaxDynamicSharedMemorySize, FA_SMEM);
    cudaFuncSetAttribute(attention_phase2, cudaFuncAttributeMaxDynamicSharedMemorySize, P2_SMEM);

    const int nSE = SEQ * EMB;

    split_pair<<<nSE / 256, 256>>>(x, BF(xhi), BF(xlo), nSE);

    // QKV: Q (1-prod, prescaled log2e/32), K (1-prod), V (3-prod fp32)
    proj_gemm<<<dim3(EMB / 64, SEQ / 256, 3), 256, SMEM3>>>(
        BF(xhi), BF(xlo), Wq, Wk, Wv, bq, bk, bv,
        BF(Qhi), BF(Khi), FL(Vf), 0);

    transpose_f16<<<dim3(EMB / 32, SEQ / 32), dim3(32, 8)>>>(FL(Vf), (__half*)Vt16_v);

    // attention phase 1 (512 threads): softmax stats + ctx
    attention_phase1<<<dim3(SEQ / 128, NH), 512, FA_SMEM>>>(
        BF(Qhi), BF(Khi), (const __half*)Vt16_v, FL(invs), BF(chi), BF(clo));

    // out = ctx @ Wo^T + bo (full 3-product)
    proj_gemm<<<dim3(EMB / 64, SEQ / 256, 1), 256, SMEM3>>>(
        BF(chi), BF(clo), Wo, nullptr, nullptr, bo, nullptr, nullptr,
        nullptr, nullptr, out, 1);

    // attention phase 2: write normalized attn (P = 2^s)
    attention_phase2<<<dim3(SEQ / 128, NH), 256, P2_SMEM>>>(
        BF(Qhi), BF(Khi), FL(invs), attn);
#undef BF
#undef FL
}